// round 15
// baseline (speedup 1.0000x reference)
#include <cuda_runtime.h>

// ---------------------------------------------------------------------------
// DecGreenNet_product_CP3 — algebraically collapsed (R8 structure):
//   out[i] = c + sum_h v[h] * tanh(x_i . Wx1[:,h] + bx1[h])
//   s_br = (sum_n y_n h_n) @ Wq2_br + (sum_n y_n) * bq2_br
//   rhs[b,d,f] = sum_x s0[b,x] s1[d,x] s2[f,x];  v = Wx2 @ rhs;  c = bx2 . rhs
//
// R15 = R8 + (a) A's tanh_acc down to 1 MUFU op (R14-validated numerics),
// (b) kernelC per-THREAD 2:1 interleave of MUFU tanh.approx and a MUFU-free
// Pade[7/6]+FMA-Newton tanh.  Per 3-h group: MUFU 128 cyc, issue 134, FMA
// 120 (vs 192 MUFU pure) -> ~30% below the rt16 ceiling C is pinned at.
// (R12 failed: its rcp WAS MUFU.  R13 failed: warp-level split imbalance.
//  This is the untested per-thread + FMA-recip combination.)
// ---------------------------------------------------------------------------

#define PI_F 3.14159265358979323846f

__device__ float g_part[3][128][128];  // per-branch per-chunk weighted-tanh sums
__device__ float g_party[3][128];      // per-branch per-chunk sum of y
__device__ float g_v[512];
__device__ float g_c;

__device__ __forceinline__ float tanh_mufu(float x) {
    float y;
    asm("tanh.approx.f32 %0, %1;" : "=f"(y) : "f"(x));
    return y;
}
// accurate tanh with ONE MUFU op (R14-validated: rel_err 4.47e-6):
//   tanh(z) = 1 - 2/(e^{2z}+1); reciprocal via magic guess + 3 FMA-Newton.
__device__ __forceinline__ float tanh_acc(float z) {
    const float d = __expf(2.0f * z) + 1.0f;      // 1 MUFU (ex2)
    float y = __int_as_float(0x7EF311C3 - __float_as_int(d));
    y = y * fmaf(-d, y, 2.0f);
    y = y * fmaf(-d, y, 2.0f);
    y = y * fmaf(-d, y, 2.0f);
    return fmaf(-2.0f, y, 1.0f);
}
// MUFU-free tanh (R13-validated numerics): Pade[7/6], clamp +-4.97,
// reciprocal via magic guess + 3 FMA-Newton.  Zero MUFU ops.
__device__ __forceinline__ float tanh_nomufu(float z) {
    const float zc = fminf(fmaxf(z, -4.97f), 4.97f);
    const float t  = zc * zc;
    const float p  = zc * fmaf(t, fmaf(t, t + 378.0f, 17325.0f), 135135.0f);
    const float q  = fmaf(t, fmaf(t, fmaf(t, 28.0f, 3150.0f), 62370.0f), 135135.0f);
    float y = __int_as_float(0x7EF311C3 - __float_as_int(q));
    y = y * fmaf(-q, y, 2.0f);
    y = y * fmaf(-q, y, 2.0f);
    y = y * fmaf(-q, y, 2.0f);
    return p * y;
}

// ---------------------------------------------------------------------------
// Kernel A: branch partials.  grid (128, 3) x 512 threads; chunk = 64 nodes.
// No pre-loop barrier: each warp loads 16 nodes into lanes, broadcasts by shfl.
// ---------------------------------------------------------------------------
__global__ void __launch_bounds__(512) kernelA(
        const float* __restrict__ q0, const float* __restrict__ q1,
        const float* __restrict__ q2,
        const float* __restrict__ w0, const float* __restrict__ w1,
        const float* __restrict__ w2,
        const float* __restrict__ c0, const float* __restrict__ c1,
        const float* __restrict__ c2,
        const float* __restrict__ eq)
{
    const int br = blockIdx.y;
    const float* qx = (br == 0) ? q0 : ((br == 1) ? q1 : q2);
    const float* W1 = (br == 0) ? w0 : ((br == 1) ? w1 : w2);
    const float* B1 = (br == 0) ? c0 : ((br == 1) ? c1 : c2);

    __shared__ float pacc[4][128];
    __shared__ float sy64[64];

    const int t    = threadIdx.x;
    const int lane = t & 31;
    const int w    = t >> 5;          // 0..15
    const int grp  = w >> 2;          // 0..3 -> which 16 nodes
    const int j    = ((w & 3) << 5) + lane;

    const float pe = PI_F * eq[0];

    float q = 0.f, y = 0.f;
    if (lane < 16) {
        q = qx[blockIdx.x * 64 + grp * 16 + lane];
        y = sinf(pe * q);
        if ((w & 3) == 0) sy64[grp * 16 + lane] = y;   // for sum_y only
    }

    const float wj = W1[j];
    const float bj = B1[j];
    float acc0 = 0.f, acc1 = 0.f;     // 2 chains for ILP
#pragma unroll
    for (int k = 0; k < 16; k += 2) {
        const float qa = __shfl_sync(0xffffffffu, q, k);
        const float ya = __shfl_sync(0xffffffffu, y, k);
        const float qb = __shfl_sync(0xffffffffu, q, k + 1);
        const float yb = __shfl_sync(0xffffffffu, y, k + 1);
        acc0 = fmaf(ya, tanh_acc(fmaf(qa, wj, bj)), acc0);
        acc1 = fmaf(yb, tanh_acc(fmaf(qb, wj, bj)), acc1);
    }
    pacc[grp][j] = acc0 + acc1;
    __syncthreads();

    if (t < 128) {
        g_part[br][blockIdx.x][t] =
            pacc[0][t] + pacc[1][t] + pacc[2][t] + pacc[3][t];
    } else if (w == 4) {              // one warp reduces sum_y
        float s = sy64[lane] + sy64[lane + 32];
#pragma unroll
        for (int o = 16; o; o >>= 1) s += __shfl_xor_sync(0xffffffffu, s, o);
        if (lane == 0) g_party[br][blockIdx.x] = s;
    }
}

// ---------------------------------------------------------------------------
// Kernel BV: grid 64 x 512.  Every block redundantly computes the tiny
// phases 1-3 (identical deterministic results), then its own 8 rows of
// v = Wx2 @ rhs.  Keeps the 1MB Wx2 stream spread over 64 SMs.
// ---------------------------------------------------------------------------
__global__ void __launch_bounds__(512) kernelBV(
        const float* __restrict__ Wq02, const float* __restrict__ bq02,
        const float* __restrict__ Wq12, const float* __restrict__ bq12,
        const float* __restrict__ Wq22, const float* __restrict__ bq22,
        const float* __restrict__ bx2,  const float* __restrict__ Wx2)
{
    __shared__ float wh[3][128];
    __shared__ float sumy[3];
    __shared__ float s_sh[3][128];
    __shared__ __align__(16) float rsh[512];
    __shared__ float red[512];

    const int t = threadIdx.x;

    // phase 1: reduce per-chunk partials (128 chunks)
    if (t < 384) {
        const int br = t >> 7, j = t & 127;
        float a = 0.f;
#pragma unroll 16
        for (int blk = 0; blk < 128; blk++) a += g_part[br][blk][j];
        wh[br][j] = a;
    } else if (t < 387) {
        const int br = t - 384;
        float s = 0.f;
#pragma unroll 16
        for (int blk = 0; blk < 128; blk++) s += g_party[br][blk];
        sumy[br] = s;
    }
    __syncthreads();

    // phase 2: s_br = wh_br @ Wq2_br + sumy_br * bq2_br (coalesced columns)
    if (t < 384) {
        const int br = t >> 7, c = t & 127;
        const float* W2 = (br == 0) ? Wq02 : ((br == 1) ? Wq12 : Wq22);
        const float* B2 = (br == 0) ? bq02 : ((br == 1) ? bq12 : bq22);
        float a = sumy[br] * B2[c];
#pragma unroll 16
        for (int j = 0; j < 128; j++) a = fmaf(wh[br][j], W2[j * 128 + c], a);
        s_sh[br][c] = a;                   // c = b*16 + x
    }
    __syncthreads();

    // phase 3: rhs + c
    if (t < 512) {
        const int b = t >> 6, d = (t >> 3) & 7, f = t & 7;
        float r = 0.f;
#pragma unroll
        for (int x = 0; x < 16; x++)
            r += s_sh[0][b * 16 + x] * s_sh[1][d * 16 + x] * s_sh[2][f * 16 + x];
        rsh[t] = r;
        red[t] = bx2[t] * r;
    }
    __syncthreads();
    for (int off = 256; off > 0; off >>= 1) {
        if (t < off) red[t] += red[t + off];
        __syncthreads();
    }
    if (blockIdx.x == 0 && t == 0) g_c = red[0];

    // phase V: 8 rows of v per block (warp per row; warps 8..15 idle)
    const int wp   = t >> 5;
    const int lane = t & 31;
    if (wp < 8) {
        const int h = blockIdx.x * 8 + wp;
        const float4* row4 = (const float4*)(Wx2 + h * 512);
        const float4* r4   = (const float4*)rsh;
        float a = 0.f;
#pragma unroll
        for (int k = lane; k < 128; k += 32) {
            const float4 w = row4[k];
            const float4 r = r4[k];
            a = fmaf(w.x, r.x, fmaf(w.y, r.y, fmaf(w.z, r.z, fmaf(w.w, r.w, a))));
        }
#pragma unroll
        for (int o = 16; o; o >>= 1) a += __shfl_xor_sync(0xffffffffu, a, o);
        if (lane == 0) g_v[h] = a;
    }
}

// ---------------------------------------------------------------------------
// Kernel C: main batch.  256 threads = 8 warps; warp = 64 h (broadcast LDS,
// conflict-free), lane = 4 rows.  Per-THREAD 2:1 interleave: h-groups of 3 =
// 2x MUFU tanh.approx + 1x MUFU-free Pade; 63 = 21 groups, + 1 MUFU tail.
// Grid 512.
// ---------------------------------------------------------------------------
__global__ void __launch_bounds__(256) kernelC(const float* __restrict__ X,
                                               const float* __restrict__ Wx1,
                                               const float* __restrict__ bx1,
                                               float* __restrict__ out, int Bn)
{
    __shared__ float4 wt[512];        // {Wx1[0,h], Wx1[1,h], Wx1[2,h], bx1[h]}
    __shared__ float  vs[512];
    __shared__ __align__(16) float pp[8][128];   // [warp][row-in-block]

    const int t = threadIdx.x;
#pragma unroll
    for (int h = t; h < 512; h += 256) {
        wt[h] = make_float4(Wx1[h], Wx1[512 + h], Wx1[1024 + h], bx1[h]);
        vs[h] = g_v[h];
    }
    __syncthreads();

    const int w    = t >> 5;          // 0..7  (h-split)
    const int lane = t & 31;          // 4 rows per lane
    const int h0   = w << 6;          // 64 h per warp
    const int r0   = blockIdx.x * 128 + lane * 4;

    float xv[12];                     // 4 rows x 3 coords
    if (r0 + 3 < Bn) {
        const float4* xp = (const float4*)(X + r0 * 3);   // 16B-aligned
#pragma unroll
        for (int q = 0; q < 3; q++) {
            const float4 v4 = xp[q];
            xv[q * 4 + 0] = v4.x; xv[q * 4 + 1] = v4.y;
            xv[q * 4 + 2] = v4.z; xv[q * 4 + 3] = v4.w;
        }
    } else {
#pragma unroll
        for (int q = 0; q < 12; q++) {
            const int gi = r0 * 3 + q;
            xv[q] = (gi < Bn * 3) ? X[gi] : 0.f;
        }
    }

    float a0 = 0.f, a1 = 0.f, a2 = 0.f, a3 = 0.f;

    // 21 groups of (MUFU, MUFU, FMA-Newton) + 1 MUFU tail = 64 h
#pragma unroll 3
    for (int g = 0; g < 21; g++) {
        const int hb = h0 + g * 3;
#pragma unroll
        for (int s = 0; s < 2; s++) {       // 2 MUFU channels
            const float4 wv = wt[hb + s];   // warp-uniform: broadcast
            const float  vv = vs[hb + s];
            const float z0 = fmaf(xv[2],  wv.z, fmaf(xv[1],  wv.y, fmaf(xv[0], wv.x, wv.w)));
            const float z1 = fmaf(xv[5],  wv.z, fmaf(xv[4],  wv.y, fmaf(xv[3], wv.x, wv.w)));
            const float z2 = fmaf(xv[8],  wv.z, fmaf(xv[7],  wv.y, fmaf(xv[6], wv.x, wv.w)));
            const float z3 = fmaf(xv[11], wv.z, fmaf(xv[10], wv.y, fmaf(xv[9], wv.x, wv.w)));
            a0 = fmaf(vv, tanh_mufu(z0), a0);
            a1 = fmaf(vv, tanh_mufu(z1), a1);
            a2 = fmaf(vv, tanh_mufu(z2), a2);
            a3 = fmaf(vv, tanh_mufu(z3), a3);
        }
        {                                    // 1 MUFU-free channel
            const float4 wv = wt[hb + 2];
            const float  vv = vs[hb + 2];
            const float z0 = fmaf(xv[2],  wv.z, fmaf(xv[1],  wv.y, fmaf(xv[0], wv.x, wv.w)));
            const float z1 = fmaf(xv[5],  wv.z, fmaf(xv[4],  wv.y, fmaf(xv[3], wv.x, wv.w)));
            const float z2 = fmaf(xv[8],  wv.z, fmaf(xv[7],  wv.y, fmaf(xv[6], wv.x, wv.w)));
            const float z3 = fmaf(xv[11], wv.z, fmaf(xv[10], wv.y, fmaf(xv[9], wv.x, wv.w)));
            a0 = fmaf(vv, tanh_nomufu(z0), a0);
            a1 = fmaf(vv, tanh_nomufu(z1), a1);
            a2 = fmaf(vv, tanh_nomufu(z2), a2);
            a3 = fmaf(vv, tanh_nomufu(z3), a3);
        }
    }
    {   // tail: h = h0 + 63, MUFU
        const float4 wv = wt[h0 + 63];
        const float  vv = vs[h0 + 63];
        const float z0 = fmaf(xv[2],  wv.z, fmaf(xv[1],  wv.y, fmaf(xv[0], wv.x, wv.w)));
        const float z1 = fmaf(xv[5],  wv.z, fmaf(xv[4],  wv.y, fmaf(xv[3], wv.x, wv.w)));
        const float z2 = fmaf(xv[8],  wv.z, fmaf(xv[7],  wv.y, fmaf(xv[6], wv.x, wv.w)));
        const float z3 = fmaf(xv[11], wv.z, fmaf(xv[10], wv.y, fmaf(xv[9], wv.x, wv.w)));
        a0 = fmaf(vv, tanh_mufu(z0), a0);
        a1 = fmaf(vv, tanh_mufu(z1), a1);
        a2 = fmaf(vv, tanh_mufu(z2), a2);
        a3 = fmaf(vv, tanh_mufu(z3), a3);
    }

    // pp[w][lane*4 .. +3]: one conflict-free STS.128 per thread
    *((float4*)&pp[w][lane * 4]) = make_float4(a0, a1, a2, a3);
    __syncthreads();

    if (t < 128) {
        float s = g_c;
#pragma unroll
        for (int w2 = 0; w2 < 8; w2++) s += pp[w2][t];
        const int oi = blockIdx.x * 128 + t;
        if (oi < Bn) out[oi] = s;
    }
}

// ---------------------------------------------------------------------------
extern "C" void kernel_launch(void* const* d_in, const int* in_sizes, int n_in,
                              void* d_out, int out_size)
{
    const float* input = (const float*)d_in[0];
    const float* eq    = (const float*)d_in[1];
    const float* q0    = (const float*)d_in[2];
    const float* q1    = (const float*)d_in[3];
    const float* q2    = (const float*)d_in[4];
    const float* Wx1   = (const float*)d_in[5];
    const float* bx1   = (const float*)d_in[6];
    const float* Wx2   = (const float*)d_in[7];
    const float* bx2   = (const float*)d_in[8];
    const float* Wq01  = (const float*)d_in[9];
    const float* bq01  = (const float*)d_in[10];
    const float* Wq02  = (const float*)d_in[11];
    const float* bq02  = (const float*)d_in[12];
    const float* Wq11  = (const float*)d_in[13];
    const float* bq11  = (const float*)d_in[14];
    const float* Wq12  = (const float*)d_in[15];
    const float* bq12  = (const float*)d_in[16];
    const float* Wq21  = (const float*)d_in[17];
    const float* bq21  = (const float*)d_in[18];
    const float* Wq22  = (const float*)d_in[19];
    const float* bq22  = (const float*)d_in[20];

    const int N  = in_sizes[2];          // 8192 quad nodes
    const int Bn = in_sizes[0] / 3;      // 65536 rows
    const int nblkA = N / 64;            // 128 chunks of 64 nodes

    kernelA<<<dim3(nblkA, 3), 512>>>(q0, q1, q2,
                                     Wq01, Wq11, Wq21,
                                     bq01, bq11, bq21, eq);
    kernelBV<<<64, 512>>>(Wq02, bq02, Wq12, bq12, Wq22, bq22, bx2, Wx2);
    kernelC<<<(Bn + 127) / 128, 256>>>(input, Wx1, bx1, (float*)d_out, Bn);
}

// round 16
// speedup vs baseline: 1.1871x; 1.1871x over previous
#include <cuda_runtime.h>

// ---------------------------------------------------------------------------
// DecGreenNet_product_CP3 — algebraically collapsed (R8 structure, locked):
//   out[i] = c + sum_h v[h] * tanh(x_i . Wx1[:,h] + bx1[h])
//   s_br = (sum_n y_n h_n) @ Wq2_br + (sum_n y_n) * bq2_br
//   rhs[b,d,f] = sum_x s0[b,x] s1[d,x] s2[f,x];  v = Wx2 @ rhs;  c = bx2 . rhs
//
// R16: kernelC = R8 pure-MUFU verbatim (rt16 ceiling; 4 hybrid attempts all
// regressed — frozen).  kernelA: 4 ILP chains (was 2; was chain-latency
// bound at issue 55%) + 1-MUFU tanh_acc (R14-validated).  kernelBV: grid 32
// with 16 v-rows/block (halves redundant phase-1..3 work, no idle warps).
// ---------------------------------------------------------------------------

#define PI_F 3.14159265358979323846f

__device__ float g_part[3][128][128];  // per-branch per-chunk weighted-tanh sums
__device__ float g_party[3][128];      // per-branch per-chunk sum of y
__device__ float g_v[512];
__device__ float g_c;

__device__ __forceinline__ float tanh_mufu(float x) {
    float y;
    asm("tanh.approx.f32 %0, %1;" : "=f"(y) : "f"(x));
    return y;
}
// accurate tanh with ONE MUFU op (R14-validated: rel_err 4.47e-6):
//   tanh(z) = 1 - 2/(e^{2z}+1); reciprocal via magic guess + 3 FMA-Newton.
__device__ __forceinline__ float tanh_acc(float z) {
    const float d = __expf(2.0f * z) + 1.0f;      // 1 MUFU (ex2)
    float y = __int_as_float(0x7EF311C3 - __float_as_int(d));
    y = y * fmaf(-d, y, 2.0f);
    y = y * fmaf(-d, y, 2.0f);
    y = y * fmaf(-d, y, 2.0f);
    return fmaf(-2.0f, y, 1.0f);
}

// ---------------------------------------------------------------------------
// Kernel A: branch partials.  grid (128, 3) x 512 threads; chunk = 64 nodes.
// Warp loads 16 nodes into lanes, broadcasts by shfl.  4 accumulator chains
// (4 nodes in flight per thread) — halves the exposed exp->Newton latency
// vs the 2-chain R8 version (issue was 55%).
// ---------------------------------------------------------------------------
__global__ void __launch_bounds__(512) kernelA(
        const float* __restrict__ q0, const float* __restrict__ q1,
        const float* __restrict__ q2,
        const float* __restrict__ w0, const float* __restrict__ w1,
        const float* __restrict__ w2,
        const float* __restrict__ c0, const float* __restrict__ c1,
        const float* __restrict__ c2,
        const float* __restrict__ eq)
{
    const int br = blockIdx.y;
    const float* qx = (br == 0) ? q0 : ((br == 1) ? q1 : q2);
    const float* W1 = (br == 0) ? w0 : ((br == 1) ? w1 : w2);
    const float* B1 = (br == 0) ? c0 : ((br == 1) ? c1 : c2);

    __shared__ float pacc[4][128];
    __shared__ float sy64[64];

    const int t    = threadIdx.x;
    const int lane = t & 31;
    const int w    = t >> 5;          // 0..15
    const int grp  = w >> 2;          // 0..3 -> which 16 nodes
    const int j    = ((w & 3) << 5) + lane;

    const float pe = PI_F * eq[0];

    float q = 0.f, y = 0.f;
    if (lane < 16) {
        q = qx[blockIdx.x * 64 + grp * 16 + lane];
        y = sinf(pe * q);
        if ((w & 3) == 0) sy64[grp * 16 + lane] = y;   // for sum_y only
    }

    const float wj = W1[j];
    const float bj = B1[j];
    float acc0 = 0.f, acc1 = 0.f, acc2 = 0.f, acc3 = 0.f;
#pragma unroll
    for (int k = 0; k < 16; k += 4) {
        const float qa = __shfl_sync(0xffffffffu, q, k);
        const float ya = __shfl_sync(0xffffffffu, y, k);
        const float qb = __shfl_sync(0xffffffffu, q, k + 1);
        const float yb = __shfl_sync(0xffffffffu, y, k + 1);
        const float qc = __shfl_sync(0xffffffffu, q, k + 2);
        const float yc = __shfl_sync(0xffffffffu, y, k + 2);
        const float qd = __shfl_sync(0xffffffffu, q, k + 3);
        const float yd = __shfl_sync(0xffffffffu, y, k + 3);
        acc0 = fmaf(ya, tanh_acc(fmaf(qa, wj, bj)), acc0);
        acc1 = fmaf(yb, tanh_acc(fmaf(qb, wj, bj)), acc1);
        acc2 = fmaf(yc, tanh_acc(fmaf(qc, wj, bj)), acc2);
        acc3 = fmaf(yd, tanh_acc(fmaf(qd, wj, bj)), acc3);
    }
    pacc[grp][j] = (acc0 + acc1) + (acc2 + acc3);
    __syncthreads();

    if (t < 128) {
        g_part[br][blockIdx.x][t] =
            pacc[0][t] + pacc[1][t] + pacc[2][t] + pacc[3][t];
    } else if (w == 4) {              // one warp reduces sum_y
        float s = sy64[lane] + sy64[lane + 32];
#pragma unroll
        for (int o = 16; o; o >>= 1) s += __shfl_xor_sync(0xffffffffu, s, o);
        if (lane == 0) g_party[br][blockIdx.x] = s;
    }
}

// ---------------------------------------------------------------------------
// Kernel BV: grid 32 x 512.  Every block redundantly computes the tiny
// phases 1-3 (identical deterministic results), then its own 16 rows of
// v = Wx2 @ rhs (all 16 warps active).  Half the redundant work of the
// 64-block version; the 1MB Wx2 stream still spreads over 32 SMs.
// ---------------------------------------------------------------------------
__global__ void __launch_bounds__(512) kernelBV(
        const float* __restrict__ Wq02, const float* __restrict__ bq02,
        const float* __restrict__ Wq12, const float* __restrict__ bq12,
        const float* __restrict__ Wq22, const float* __restrict__ bq22,
        const float* __restrict__ bx2,  const float* __restrict__ Wx2)
{
    __shared__ float wh[3][128];
    __shared__ float sumy[3];
    __shared__ float s_sh[3][128];
    __shared__ __align__(16) float rsh[512];
    __shared__ float red[512];

    const int t = threadIdx.x;

    // phase 1: reduce per-chunk partials (128 chunks)
    if (t < 384) {
        const int br = t >> 7, j = t & 127;
        float a = 0.f;
#pragma unroll 16
        for (int blk = 0; blk < 128; blk++) a += g_part[br][blk][j];
        wh[br][j] = a;
    } else if (t < 387) {
        const int br = t - 384;
        float s = 0.f;
#pragma unroll 16
        for (int blk = 0; blk < 128; blk++) s += g_party[br][blk];
        sumy[br] = s;
    }
    __syncthreads();

    // phase 2: s_br = wh_br @ Wq2_br + sumy_br * bq2_br (coalesced columns)
    if (t < 384) {
        const int br = t >> 7, c = t & 127;
        const float* W2 = (br == 0) ? Wq02 : ((br == 1) ? Wq12 : Wq22);
        const float* B2 = (br == 0) ? bq02 : ((br == 1) ? bq12 : bq22);
        float a = sumy[br] * B2[c];
#pragma unroll 16
        for (int j = 0; j < 128; j++) a = fmaf(wh[br][j], W2[j * 128 + c], a);
        s_sh[br][c] = a;                   // c = b*16 + x
    }
    __syncthreads();

    // phase 3: rhs + c
    if (t < 512) {
        const int b = t >> 6, d = (t >> 3) & 7, f = t & 7;
        float r = 0.f;
#pragma unroll
        for (int x = 0; x < 16; x++)
            r += s_sh[0][b * 16 + x] * s_sh[1][d * 16 + x] * s_sh[2][f * 16 + x];
        rsh[t] = r;
        red[t] = bx2[t] * r;
    }
    __syncthreads();
    for (int off = 256; off > 0; off >>= 1) {
        if (t < off) red[t] += red[t + off];
        __syncthreads();
    }
    if (blockIdx.x == 0 && t == 0) g_c = red[0];

    // phase V: 16 rows of v per block (warp per row — all warps active)
    const int wp   = t >> 5;
    const int lane = t & 31;
    {
        const int h = blockIdx.x * 16 + wp;
        const float4* row4 = (const float4*)(Wx2 + h * 512);
        const float4* r4   = (const float4*)rsh;
        float a = 0.f;
#pragma unroll
        for (int k = lane; k < 128; k += 32) {
            const float4 w = row4[k];
            const float4 r = r4[k];
            a = fmaf(w.x, r.x, fmaf(w.y, r.y, fmaf(w.z, r.z, fmaf(w.w, r.w, a))));
        }
#pragma unroll
        for (int o = 16; o; o >>= 1) a += __shfl_xor_sync(0xffffffffu, a, o);
        if (lane == 0) g_v[h] = a;
    }
}

// ---------------------------------------------------------------------------
// Kernel C: main batch (R8 pure-MUFU, verbatim — FROZEN).  256 threads =
// 8 warps; warp = 64 h (broadcast LDS, conflict-free), lane = 4 rows.
// At the tanh.approx rt16 MUFU ceiling — proven optimal mapping.
// ---------------------------------------------------------------------------
__global__ void __launch_bounds__(256) kernelC(const float* __restrict__ X,
                                               const float* __restrict__ Wx1,
                                               const float* __restrict__ bx1,
                                               float* __restrict__ out, int Bn)
{
    __shared__ float4 wt[512];        // {Wx1[0,h], Wx1[1,h], Wx1[2,h], bx1[h]}
    __shared__ float  vs[512];
    __shared__ __align__(16) float pp[8][128];   // [warp][row-in-block]

    const int t = threadIdx.x;
#pragma unroll
    for (int h = t; h < 512; h += 256) {
        wt[h] = make_float4(Wx1[h], Wx1[512 + h], Wx1[1024 + h], bx1[h]);
        vs[h] = g_v[h];
    }
    __syncthreads();

    const int w    = t >> 5;          // 0..7  (h-split)
    const int lane = t & 31;          // 4 rows per lane
    const int h0   = w << 6;          // 64 h per warp
    const int r0   = blockIdx.x * 128 + lane * 4;

    float xv[12];                     // 4 rows x 3 coords
    if (r0 + 3 < Bn) {
        const float4* xp = (const float4*)(X + r0 * 3);   // 16B-aligned
#pragma unroll
        for (int q = 0; q < 3; q++) {
            const float4 v4 = xp[q];
            xv[q * 4 + 0] = v4.x; xv[q * 4 + 1] = v4.y;
            xv[q * 4 + 2] = v4.z; xv[q * 4 + 3] = v4.w;
        }
    } else {
#pragma unroll
        for (int q = 0; q < 12; q++) {
            const int gi = r0 * 3 + q;
            xv[q] = (gi < Bn * 3) ? X[gi] : 0.f;
        }
    }

    float a0 = 0.f, a1 = 0.f, a2 = 0.f, a3 = 0.f;
#pragma unroll 8
    for (int hh = 0; hh < 64; hh++) {
        const float4 wv = wt[h0 + hh];    // warp-uniform: broadcast
        const float  vv = vs[h0 + hh];    // broadcast
        const float z0 = fmaf(xv[2],  wv.z, fmaf(xv[1],  wv.y, fmaf(xv[0], wv.x, wv.w)));
        const float z1 = fmaf(xv[5],  wv.z, fmaf(xv[4],  wv.y, fmaf(xv[3], wv.x, wv.w)));
        const float z2 = fmaf(xv[8],  wv.z, fmaf(xv[7],  wv.y, fmaf(xv[6], wv.x, wv.w)));
        const float z3 = fmaf(xv[11], wv.z, fmaf(xv[10], wv.y, fmaf(xv[9], wv.x, wv.w)));
        a0 = fmaf(vv, tanh_mufu(z0), a0);
        a1 = fmaf(vv, tanh_mufu(z1), a1);
        a2 = fmaf(vv, tanh_mufu(z2), a2);
        a3 = fmaf(vv, tanh_mufu(z3), a3);
    }

    // pp[w][lane*4 .. +3]: one conflict-free STS.128 per thread
    *((float4*)&pp[w][lane * 4]) = make_float4(a0, a1, a2, a3);
    __syncthreads();

    if (t < 128) {
        float s = g_c;
#pragma unroll
        for (int w2 = 0; w2 < 8; w2++) s += pp[w2][t];
        const int oi = blockIdx.x * 128 + t;
        if (oi < Bn) out[oi] = s;
    }
}

// ---------------------------------------------------------------------------
extern "C" void kernel_launch(void* const* d_in, const int* in_sizes, int n_in,
                              void* d_out, int out_size)
{
    const float* input = (const float*)d_in[0];
    const float* eq    = (const float*)d_in[1];
    const float* q0    = (const float*)d_in[2];
    const float* q1    = (const float*)d_in[3];
    const float* q2    = (const float*)d_in[4];
    const float* Wx1   = (const float*)d_in[5];
    const float* bx1   = (const float*)d_in[6];
    const float* Wx2   = (const float*)d_in[7];
    const float* bx2   = (const float*)d_in[8];
    const float* Wq01  = (const float*)d_in[9];
    const float* bq01  = (const float*)d_in[10];
    const float* Wq02  = (const float*)d_in[11];
    const float* bq02  = (const float*)d_in[12];
    const float* Wq11  = (const float*)d_in[13];
    const float* bq11  = (const float*)d_in[14];
    const float* Wq12  = (const float*)d_in[15];
    const float* bq12  = (const float*)d_in[16];
    const float* Wq21  = (const float*)d_in[17];
    const float* bq21  = (const float*)d_in[18];
    const float* Wq22  = (const float*)d_in[19];
    const float* bq22  = (const float*)d_in[20];

    const int N  = in_sizes[2];          // 8192 quad nodes
    const int Bn = in_sizes[0] / 3;      // 65536 rows
    const int nblkA = N / 64;            // 128 chunks of 64 nodes

    kernelA<<<dim3(nblkA, 3), 512>>>(q0, q1, q2,
                                     Wq01, Wq11, Wq21,
                                     bq01, bq11, bq21, eq);
    kernelBV<<<32, 512>>>(Wq02, bq02, Wq12, bq12, Wq22, bq22, bx2, Wx2);
    kernelC<<<(Bn + 127) / 128, 256>>>(input, Wx1, bx1, (float*)d_out, Bn);
}